// round 1
// baseline (speedup 1.0000x reference)
#include <cuda_runtime.h>

#define B 32
#define NN 128
#define DW 135
#define OBS 7
#define F 64
#define OD 4

// -------- device scratch (no allocations allowed) --------
__device__ float g_norm[B][NN];
__device__ int   g_maxnorm;
__device__ float g_c[B][NN][F];        // c[j][f], f<63 valid, [63]=0
__device__ float g_cur[2][B][NN][F];
__device__ float g_edge[B][NN][F];
__device__ float g_P[B][OD];
__device__ float g_A[B][NN][OD];
__device__ float g_C[B][NN][OD];

// ---------------- K0: reset ----------------
__global__ void k0_reset() { g_maxnorm = 0; }

// ---------------- K1: norm + c[j] + init_emb ----------------
__global__ void __launch_bounds__(128) k1_init(const float* __restrict__ obs,
                                               const float* __restrict__ Wi,
                                               const float* __restrict__ Wee) {
    int b = blockIdx.x;
    int j = threadIdx.x;              // node index 0..127
    __shared__ float sWi[F * OBS];    // 448
    __shared__ float sWee[63 * OBS];  // 441 (cols 1..7 of W_edge_embed)
    for (int t = j; t < F * OBS; t += 128) sWi[t] = Wi[t];
    for (int t = j; t < 63 * OBS; t += 128) {
        int f = t / OBS, k = t % OBS;
        sWee[t] = Wee[f * 8 + 1 + k];
    }
    __syncthreads();

    const float* ob = obs + (size_t)b * NN * DW;

    // norm[b][j] = count of nonzeros in column j of adj
    int cnt = 0;
#pragma unroll 8
    for (int i = 0; i < NN; i++)
        cnt += (ob[i * DW + OBS + j] != 0.0f);
    if (cnt == 0) cnt = 1;
    g_norm[b][j] = (float)cnt;
    atomicMax(&g_maxnorm, cnt);

    float nf[OBS];
#pragma unroll
    for (int k = 0; k < OBS; k++) nf[k] = ob[j * DW + k];

#pragma unroll 4
    for (int f = 0; f < F; f++) {
        float a = 0.f;
#pragma unroll
        for (int k = 0; k < OBS; k++) a = fmaf(nf[k], sWi[f * OBS + k], a);
        g_cur[0][b][j][f] = fmaxf(a, 0.f);
    }
#pragma unroll 4
    for (int f = 0; f < 63; f++) {
        float a = 0.f;
#pragma unroll
        for (int k = 0; k < OBS; k++) a = fmaf(nf[k], sWee[f * OBS + k], a);
        g_c[b][j][f] = a;
    }
    g_c[b][j][63] = 0.f;
}

// ---------------- K2: edge aggregation + edge_emb ----------------
#define K2_NPB 8
__global__ void __launch_bounds__(512) k2_edge(const float* __restrict__ obs,
                                               const float* __restrict__ Wee,
                                               const float* __restrict__ Wef) {
    int b = blockIdx.y;
    int itile = blockIdx.x;                 // 16 tiles of 8 nodes
    int tid = threadIdx.x;
    int f = tid & 63, q = tid >> 6;         // q 0..7
    int i = itile * K2_NPB + q;

    __shared__ float s_adj[K2_NPB][NN];
    __shared__ float s_w0[F];
    __shared__ float s_WefT[F][F + 1];
    __shared__ float s_x[K2_NPB][F];

    const float* ob = obs + (size_t)b * NN * DW;
    for (int t = tid; t < K2_NPB * NN; t += 512) {
        int il = t >> 7, j = t & 127;
        s_adj[il][j] = ob[(itile * K2_NPB + il) * DW + OBS + j];
    }
    for (int t = tid; t < F * F; t += 512) {
        int ff = t >> 6, k = t & 63;
        s_WefT[k][ff] = Wef[t];
    }
    if (tid < F) s_w0[tid] = (tid < 63) ? Wee[tid * 8] : 0.f;
    __syncthreads();

    float w0 = s_w0[f];
    float s = 0.f;
    const float* crow = &g_c[b][0][f];
#pragma unroll 4
    for (int j = 0; j < NN; j++) {
        float a = s_adj[q][j];
        float e = fmaxf(fmaf(a, w0, crow[j * F]), 0.f);
        s += (a != 0.f) ? e : 0.f;
    }
    float nrm = g_norm[b][i];
    float mx = (float)g_maxnorm;
    s_x[q][f] = (f < 63) ? (s / nrm) : (nrm / mx);
    __syncthreads();

    float acc = 0.f;
#pragma unroll
    for (int k = 0; k < F; k++) acc = fmaf(s_x[q][k], s_WefT[k][f], acc);
    g_edge[b][i][f] = fmaxf(acc, 0.f);
}

// ---------------- K3: one message-passing layer ----------------
// 16 nodes per block, 256 threads = (node il = tid>>4) x (fgroup fg = tid&15, 4 f each)
#define K3_NPB 16
#define WT_STRIDE 68   // 128 rows x 68 floats, 16B-aligned float4 rows

// dynamic smem layout (floats):
//  s_WT  [128*68] = 8704
//  s_cur [128*64] = 8192
//  s_adj [16*128] = 2048
//  s_edge[16*64]  = 1024
//  s_agg [16*64]  = 1024
//  s_msg [16*64]  = 1024
//  s_inv [16]
#define K3_SMEM_FLOATS (8704 + 8192 + 2048 + 1024 + 1024 + 1024 + 16)
#define K3_SMEM_BYTES (K3_SMEM_FLOATS * 4)

__global__ void __launch_bounds__(256, 2) k3_layer(const float* __restrict__ obs,
                                                   const float* __restrict__ Wm,
                                                   const float* __restrict__ Wu,
                                                   int src, int dst) {
    extern __shared__ float sm[];
    float* s_WT   = sm;                    // transposed weight [k][f], stride 68
    float* s_cur  = s_WT + 128 * WT_STRIDE;
    float* s_adj  = s_cur + 128 * 64;
    float* s_edge = s_adj + K3_NPB * 128;
    float* s_agg  = s_edge + K3_NPB * 64;
    float* s_msg  = s_agg + K3_NPB * 64;
    float* s_inv  = s_msg + K3_NPB * 64;

    int b = blockIdx.y, tile = blockIdx.x;   // 8 tiles of 16 nodes
    int tid = threadIdx.x;
    int fg = tid & 15;                       // f = fg*4 .. fg*4+3
    int il = tid >> 4;                       // local node 0..15
    int i0 = tile * K3_NPB;
    const float* ob = obs + (size_t)b * NN * DW;

    // ---- loads ----
    for (int t = tid; t < F * 2 * F; t += 256) {     // Wm transposed: [k][f]
        int ff = t >> 7, k = t & 127;
        s_WT[k * WT_STRIDE + ff] = Wm[t];
    }
    for (int t = tid; t < 128 * 64; t += 256)
        s_cur[t] = g_cur[src][b][0][t];
    for (int t = tid; t < K3_NPB * 128; t += 256) {
        int r = t >> 7, j = t & 127;
        s_adj[t] = ob[(i0 + r) * DW + OBS + j];
    }
    for (int t = tid; t < K3_NPB * 64; t += 256) {
        int r = t >> 6, k = t & 63;
        s_edge[t] = g_edge[b][i0 + r][k];
    }
    if (tid < K3_NPB) s_inv[tid] = 1.0f / g_norm[b][i0 + tid];
    __syncthreads();

    // ---- agg = adj @ cur / norm ----
    {
        float4 a = make_float4(0.f, 0.f, 0.f, 0.f);
        const float* arow = &s_adj[il * 128];
#pragma unroll 4
        for (int j = 0; j < NN; j++) {
            float av = arow[j];
            float4 c = *(const float4*)&s_cur[j * 64 + fg * 4];
            a.x = fmaf(av, c.x, a.x);
            a.y = fmaf(av, c.y, a.y);
            a.z = fmaf(av, c.z, a.z);
            a.w = fmaf(av, c.w, a.w);
        }
        float inv = s_inv[il];
        a.x *= inv; a.y *= inv; a.z *= inv; a.w *= inv;
        *(float4*)&s_agg[il * 64 + fg * 4] = a;
    }
    __syncthreads();

    // ---- msg = relu([agg, edge] @ Wm^T) ----
    {
        float4 m = make_float4(0.f, 0.f, 0.f, 0.f);
#pragma unroll 4
        for (int k = 0; k < F; k++) {
            float av = s_agg[il * 64 + k];
            float ev = s_edge[il * 64 + k];
            float4 w1 = *(const float4*)&s_WT[k * WT_STRIDE + fg * 4];
            float4 w2 = *(const float4*)&s_WT[(F + k) * WT_STRIDE + fg * 4];
            m.x = fmaf(av, w1.x, fmaf(ev, w2.x, m.x));
            m.y = fmaf(av, w1.y, fmaf(ev, w2.y, m.y));
            m.z = fmaf(av, w1.z, fmaf(ev, w2.z, m.z));
            m.w = fmaf(av, w1.w, fmaf(ev, w2.w, m.w));
        }
        m.x = fmaxf(m.x, 0.f); m.y = fmaxf(m.y, 0.f);
        m.z = fmaxf(m.z, 0.f); m.w = fmaxf(m.w, 0.f);
        *(float4*)&s_msg[il * 64 + fg * 4] = m;
    }
    __syncthreads();

    // ---- reload weight buffer with Wu transposed ----
    for (int t = tid; t < F * 2 * F; t += 256) {
        int ff = t >> 7, k = t & 127;
        s_WT[k * WT_STRIDE + ff] = Wu[t];
    }
    __syncthreads();

    // ---- cur' = relu([cur, msg] @ Wu^T) ----
    {
        float4 u = make_float4(0.f, 0.f, 0.f, 0.f);
        const float* crow = &s_cur[(i0 + il) * 64];
#pragma unroll 4
        for (int k = 0; k < F; k++) {
            float cv = crow[k];
            float mv = s_msg[il * 64 + k];
            float4 w1 = *(const float4*)&s_WT[k * WT_STRIDE + fg * 4];
            float4 w2 = *(const float4*)&s_WT[(F + k) * WT_STRIDE + fg * 4];
            u.x = fmaf(cv, w1.x, fmaf(mv, w2.x, u.x));
            u.y = fmaf(cv, w1.y, fmaf(mv, w2.y, u.y));
            u.z = fmaf(cv, w1.z, fmaf(mv, w2.z, u.z));
            u.w = fmaf(cv, w1.w, fmaf(mv, w2.w, u.w));
        }
        u.x = fmaxf(u.x, 0.f); u.y = fmaxf(u.y, 0.f);
        u.z = fmaxf(u.z, 0.f); u.w = fmaxf(u.w, 0.f);
        *(float4*)&g_cur[dst][b][i0 + il][fg * 4] = u;
    }
}

// ---------------- K4: pool + readout precompute ----------------
__global__ void __launch_bounds__(128) k4_pool(const float* __restrict__ Wp,
                                               const float* __restrict__ Wr,
                                               const float* __restrict__ br,
                                               int src) {
    int b = blockIdx.x;
    int tid = threadIdx.x;
    __shared__ float s_part[128];
    __shared__ float s_mean[F];
    __shared__ float s_rp[F];

    {
        int f = tid & 63, h = tid >> 6;
        float acc = 0.f;
        for (int i = h; i < NN; i += 2) acc += g_cur[src][b][i][f];
        s_part[tid] = acc;
    }
    __syncthreads();
    if (tid < F) s_mean[tid] = (s_part[tid] + s_part[tid + 64]) * (1.0f / NN);
    __syncthreads();
    if (tid < F) {
        float hp = 0.f;
#pragma unroll 4
        for (int k = 0; k < F; k++) hp = fmaf(s_mean[k], Wp[tid * 64 + k], hp);
        s_rp[tid] = fmaxf(hp, 0.f);
    }
    __syncthreads();
    if (tid < OD) {
        float p = br[tid];
#pragma unroll 4
        for (int f = 0; f < F; f++) p = fmaf(s_rp[f], Wr[tid * 192 + f], p);
        g_P[b][tid] = p;
    }
    // A, C per node
    int i = tid;
    float a[OD] = {0.f, 0.f, 0.f, 0.f};
    float c[OD] = {0.f, 0.f, 0.f, 0.f};
#pragma unroll 4
    for (int k = 0; k < F; k++) {
        float r = fmaxf(g_cur[src][b][i][k], 0.f);
#pragma unroll
        for (int o = 0; o < OD; o++) {
            a[o] = fmaf(r, Wr[o * 192 + 64 + k], a[o]);
            c[o] = fmaf(r, Wr[o * 192 + 128 + k], c[o]);
        }
    }
#pragma unroll
    for (int o = 0; o < OD; o++) {
        g_A[b][i][o] = a[o];
        g_C[b][i][o] = c[o];
    }
}

// ---------------- K5: output writer ----------------
__global__ void __launch_bounds__(128) k5_out(float* __restrict__ out) {
    int b = blockIdx.y, i = blockIdx.x, j = threadIdx.x;
    float4 P = *(const float4*)&g_P[b][0];
    float4 A = *(const float4*)&g_A[b][i][0];
    float4 C = *(const float4*)&g_C[b][j][0];
    float4 r;
    r.x = P.x + A.x + C.x;
    r.y = P.y + A.y + C.y;
    r.z = P.z + A.z + C.z;
    r.w = P.w + A.w + C.w;
    ((float4*)out)[((size_t)b * NN + i) * NN + j] = r;
}

// ---------------- launch ----------------
extern "C" void kernel_launch(void* const* d_in, const int* in_sizes, int n_in,
                              void* d_out, int out_size) {
    const float* obs = (const float*)d_in[0];
    const float* Wi  = (const float*)d_in[1];
    const float* Wee = (const float*)d_in[2];
    const float* Wef = (const float*)d_in[3];
    const float* Wm  = (const float*)d_in[4];
    const float* Wu  = (const float*)d_in[5];
    const float* Wp  = (const float*)d_in[6];
    const float* Wr  = (const float*)d_in[7];
    const float* br  = (const float*)d_in[8];

    cudaFuncSetAttribute(k3_layer, cudaFuncAttributeMaxDynamicSharedMemorySize,
                         K3_SMEM_BYTES);

    k0_reset<<<1, 1>>>();
    k1_init<<<B, 128>>>(obs, Wi, Wee);
    k2_edge<<<dim3(NN / K2_NPB, B), 512>>>(obs, Wee, Wef);

    const int LW = F * 2 * F;  // 8192 floats per layer
    k3_layer<<<dim3(NN / K3_NPB, B), 256, K3_SMEM_BYTES>>>(obs, Wm + 0 * LW, Wu + 0 * LW, 0, 1);
    k3_layer<<<dim3(NN / K3_NPB, B), 256, K3_SMEM_BYTES>>>(obs, Wm + 1 * LW, Wu + 1 * LW, 1, 0);
    k3_layer<<<dim3(NN / K3_NPB, B), 256, K3_SMEM_BYTES>>>(obs, Wm + 2 * LW, Wu + 2 * LW, 0, 1);

    k4_pool<<<B, 128>>>(Wp, Wr, br, 1);
    k5_out<<<dim3(NN, B), 128>>>((float*)d_out);
}

// round 5
// speedup vs baseline: 1.3437x; 1.3437x over previous
#include <cuda_runtime.h>

#define B 32
#define NN 128
#define DW 135
#define OBS 7
#define F 64
#define OD 4

// -------- device scratch (no allocations allowed) --------
__device__ __align__(16) float g_norm[B][NN];
__device__ float g_bmax[B];
__device__ __align__(16) float g_c[B][NN][F];      // c[j][f], f<63 valid, [63]=0
__device__ __align__(16) float g_cur[2][B][NN][F];
__device__ __align__(16) float g_edge[B][NN][F];
__device__ __align__(16) float g_P[B][OD];
__device__ __align__(16) float g_A[B][NN][OD];
__device__ __align__(16) float g_C[B][NN][OD];

// ---------------- K1: norm + per-batch max + c[j] + init_emb ----------------
__global__ void __launch_bounds__(128) k1_init(const float* __restrict__ obs,
                                               const float* __restrict__ Wi,
                                               const float* __restrict__ Wee) {
    int b = blockIdx.x;
    int j = threadIdx.x;              // node index 0..127
    __shared__ float sWi[F * OBS];
    __shared__ float sWee[63 * OBS];
    __shared__ int s_cnt[128];
    for (int t = j; t < F * OBS; t += 128) sWi[t] = Wi[t];
    for (int t = j; t < 63 * OBS; t += 128) {
        int f = t / OBS, k = t % OBS;
        sWee[t] = Wee[f * 8 + 1 + k];
    }
    __syncthreads();

    const float* ob = obs + (size_t)b * NN * DW;

    int cnt = 0;
#pragma unroll 8
    for (int i = 0; i < NN; i++)
        cnt += (ob[i * DW + OBS + j] != 0.0f);
    if (cnt == 0) cnt = 1;
    g_norm[b][j] = (float)cnt;
    s_cnt[j] = cnt;

    float nf[OBS];
#pragma unroll
    for (int k = 0; k < OBS; k++) nf[k] = ob[j * DW + k];

#pragma unroll 4
    for (int f = 0; f < F; f++) {
        float a = 0.f;
#pragma unroll
        for (int k = 0; k < OBS; k++) a = fmaf(nf[k], sWi[f * OBS + k], a);
        g_cur[0][b][j][f] = fmaxf(a, 0.f);
    }
#pragma unroll 4
    for (int f = 0; f < 63; f++) {
        float a = 0.f;
#pragma unroll
        for (int k = 0; k < OBS; k++) a = fmaf(nf[k], sWee[f * OBS + k], a);
        g_c[b][j][f] = a;
    }
    g_c[b][j][63] = 0.f;

    // block max of cnt
    __syncthreads();
#pragma unroll
    for (int s = 64; s > 0; s >>= 1) {
        if (j < s) s_cnt[j] = max(s_cnt[j], s_cnt[j + s]);
        __syncthreads();
    }
    if (j == 0) g_bmax[b] = (float)s_cnt[0];
}

// ---------------- K2: edge aggregation + edge_emb ----------------
#define K2_NPB 8
// dynamic smem (floats): s_c 8192 | s_adj 1024 | s_WT 64*65=4160 | s_x 512 | s_w0 64 | s_red 33
#define K2_SMEM_FLOATS (8192 + 1024 + 4160 + 512 + 64 + 33)
#define K2_SMEM_BYTES  (K2_SMEM_FLOATS * 4)
__global__ void __launch_bounds__(512) k2_edge(const float* __restrict__ obs,
                                               const float* __restrict__ Wee,
                                               const float* __restrict__ Wef) {
    extern __shared__ float sm2[];
    float* s_c   = sm2;
    float* s_adj = s_c + 8192;
    float* s_WT  = s_adj + 1024;    // [k][f] stride 65
    float* s_x   = s_WT + 4160;
    float* s_w0  = s_x + 512;
    float* s_red = s_w0 + 64;

    int b = blockIdx.y;
    int itile = blockIdx.x;
    int tid = threadIdx.x;
    int f = tid & 63, q = tid >> 6;
    int i = itile * K2_NPB + q;

    const float* ob = obs + (size_t)b * NN * DW;

    // stage g_c[b] (coalesced float4)
    {
        const float4* src = (const float4*)&g_c[b][0][0];
        float4* dst = (float4*)s_c;
        for (int t = tid; t < 2048; t += 512) dst[t] = src[t];
    }
    for (int t = tid; t < K2_NPB * NN; t += 512) {
        int il = t >> 7, j = t & 127;
        s_adj[t] = ob[(itile * K2_NPB + il) * DW + OBS + j];
    }
    for (int t = tid; t < F * F; t += 512) {
        int ff = t >> 6, k = t & 63;
        s_WT[k * 65 + ff] = Wef[t];
    }
    if (tid < F) s_w0[tid] = (tid < 63) ? Wee[tid * 8] : 0.f;
    if (tid < 32) s_red[tid] = g_bmax[tid];
    __syncthreads();
    if (tid == 0) {
        float m = s_red[0];
        for (int t = 1; t < 32; t++) m = fmaxf(m, s_red[t]);
        s_red[32] = m;
    }
    __syncthreads();

    float w0 = s_w0[f];
    float s = 0.f;
    const float* arow = &s_adj[q * 128];
#pragma unroll 8
    for (int j = 0; j < NN; j++) {
        float a = arow[j];
        float e = fmaxf(fmaf(a, w0, s_c[j * 64 + f]), 0.f);
        s += (a != 0.f) ? e : 0.f;
    }
    float nrm = g_norm[b][i];
    float mx = s_red[32];
    s_x[q * 64 + f] = (f < 63) ? (s / nrm) : (nrm / mx);
    __syncthreads();

    float acc = 0.f;
#pragma unroll 8
    for (int k = 0; k < F; k++) acc = fmaf(s_x[q * 64 + k], s_WT[k * 65 + f], acc);
    g_edge[b][i][f] = fmaxf(acc, 0.f);
}

// ---------------- K3: one message-passing layer ----------------
// 32 nodes/block, 256 threads, 2 nodes x 4 feats per thread, both weights resident.
#define K3_NPB 32
#define WTS 68
// floats: Wm 8704 | Wu 8704 | cur 8192 | adj 4096 | edge 2048 | agg 2048 | msg 2048 | inv 32
#define K3_SMEM_FLOATS (8704 * 2 + 8192 + 4096 + 2048 * 3 + 32)
#define K3_SMEM_BYTES  (K3_SMEM_FLOATS * 4)

__global__ void __launch_bounds__(256, 1) k3_layer(const float* __restrict__ obs,
                                                   const float* __restrict__ Wm,
                                                   const float* __restrict__ Wu,
                                                   int src, int dst) {
    extern __shared__ float sm[];
    float* s_Wm   = sm;                     // [k][f] stride WTS
    float* s_Wu   = s_Wm + 128 * WTS;
    float* s_cur  = s_Wu + 128 * WTS;       // [128][64]
    float* s_adj  = s_cur + 128 * 64;       // [32][128]
    float* s_edge = s_adj + K3_NPB * 128;   // [32][64]
    float* s_agg  = s_edge + K3_NPB * 64;
    float* s_msg  = s_agg + K3_NPB * 64;
    float* s_inv  = s_msg + K3_NPB * 64;

    int b = blockIdx.y, tile = blockIdx.x;
    int tid = threadIdx.x;
    int fg = tid & 15;
    int ns = tid >> 4;          // 0..15
    int il0 = ns * 2, il1 = il0 + 1;
    int i0 = tile * K3_NPB;
    const float* ob = obs + (size_t)b * NN * DW;

    // ---- loads ----
    for (int t = tid; t < F * 2 * F; t += 256) {
        int ff = t >> 7, k = t & 127;
        s_Wm[k * WTS + ff] = Wm[t];
        s_Wu[k * WTS + ff] = Wu[t];
    }
    {
        const float4* src4 = (const float4*)&g_cur[src][b][0][0];
        float4* dst4 = (float4*)s_cur;
        for (int t = tid; t < 2048; t += 256) dst4[t] = src4[t];
        const float4* es = (const float4*)&g_edge[b][i0][0];
        float4* ed = (float4*)s_edge;
        for (int t = tid; t < 512; t += 256) ed[t] = es[t];
    }
    for (int t = tid; t < K3_NPB * 128; t += 256) {
        int r = t >> 7, j = t & 127;
        s_adj[t] = ob[(i0 + r) * DW + OBS + j];
    }
    if (tid < K3_NPB) s_inv[tid] = 1.0f / g_norm[b][i0 + tid];
    __syncthreads();

    // ---- agg = adj @ cur / norm  (2 nodes per thread) ----
    {
        float4 a0 = make_float4(0.f, 0.f, 0.f, 0.f);
        float4 a1 = make_float4(0.f, 0.f, 0.f, 0.f);
        const float* ar0 = &s_adj[il0 * 128];
        const float* ar1 = &s_adj[il1 * 128];
#pragma unroll 8
        for (int j = 0; j < NN; j++) {
            float4 c = *(const float4*)&s_cur[j * 64 + fg * 4];
            float v0 = ar0[j], v1 = ar1[j];
            a0.x = fmaf(v0, c.x, a0.x); a0.y = fmaf(v0, c.y, a0.y);
            a0.z = fmaf(v0, c.z, a0.z); a0.w = fmaf(v0, c.w, a0.w);
            a1.x = fmaf(v1, c.x, a1.x); a1.y = fmaf(v1, c.y, a1.y);
            a1.z = fmaf(v1, c.z, a1.z); a1.w = fmaf(v1, c.w, a1.w);
        }
        float i0v = s_inv[il0], i1v = s_inv[il1];
        a0.x *= i0v; a0.y *= i0v; a0.z *= i0v; a0.w *= i0v;
        a1.x *= i1v; a1.y *= i1v; a1.z *= i1v; a1.w *= i1v;
        *(float4*)&s_agg[il0 * 64 + fg * 4] = a0;
        *(float4*)&s_agg[il1 * 64 + fg * 4] = a1;
    }
    __syncthreads();

    // ---- msg = relu([agg, edge] @ Wm^T) ----
    {
        float4 m0 = make_float4(0.f, 0.f, 0.f, 0.f);
        float4 m1 = make_float4(0.f, 0.f, 0.f, 0.f);
#pragma unroll 8
        for (int k = 0; k < F; k++) {
            float4 w1 = *(const float4*)&s_Wm[k * WTS + fg * 4];
            float4 w2 = *(const float4*)&s_Wm[(F + k) * WTS + fg * 4];
            float g0 = s_agg[il0 * 64 + k], g1 = s_agg[il1 * 64 + k];
            float e0 = s_edge[il0 * 64 + k], e1 = s_edge[il1 * 64 + k];
            m0.x = fmaf(g0, w1.x, fmaf(e0, w2.x, m0.x));
            m0.y = fmaf(g0, w1.y, fmaf(e0, w2.y, m0.y));
            m0.z = fmaf(g0, w1.z, fmaf(e0, w2.z, m0.z));
            m0.w = fmaf(g0, w1.w, fmaf(e0, w2.w, m0.w));
            m1.x = fmaf(g1, w1.x, fmaf(e1, w2.x, m1.x));
            m1.y = fmaf(g1, w1.y, fmaf(e1, w2.y, m1.y));
            m1.z = fmaf(g1, w1.z, fmaf(e1, w2.z, m1.z));
            m1.w = fmaf(g1, w1.w, fmaf(e1, w2.w, m1.w));
        }
        m0.x = fmaxf(m0.x, 0.f); m0.y = fmaxf(m0.y, 0.f);
        m0.z = fmaxf(m0.z, 0.f); m0.w = fmaxf(m0.w, 0.f);
        m1.x = fmaxf(m1.x, 0.f); m1.y = fmaxf(m1.y, 0.f);
        m1.z = fmaxf(m1.z, 0.f); m1.w = fmaxf(m1.w, 0.f);
        *(float4*)&s_msg[il0 * 64 + fg * 4] = m0;
        *(float4*)&s_msg[il1 * 64 + fg * 4] = m1;
    }
    __syncthreads();

    // ---- cur' = relu([cur, msg] @ Wu^T) ----
    {
        float4 u0 = make_float4(0.f, 0.f, 0.f, 0.f);
        float4 u1 = make_float4(0.f, 0.f, 0.f, 0.f);
        const float* c0 = &s_cur[(i0 + il0) * 64];
        const float* c1 = &s_cur[(i0 + il1) * 64];
#pragma unroll 8
        for (int k = 0; k < F; k++) {
            float4 w1 = *(const float4*)&s_Wu[k * WTS + fg * 4];
            float4 w2 = *(const float4*)&s_Wu[(F + k) * WTS + fg * 4];
            float cv0 = c0[k], cv1 = c1[k];
            float mv0 = s_msg[il0 * 64 + k], mv1 = s_msg[il1 * 64 + k];
            u0.x = fmaf(cv0, w1.x, fmaf(mv0, w2.x, u0.x));
            u0.y = fmaf(cv0, w1.y, fmaf(mv0, w2.y, u0.y));
            u0.z = fmaf(cv0, w1.z, fmaf(mv0, w2.z, u0.z));
            u0.w = fmaf(cv0, w1.w, fmaf(mv0, w2.w, u0.w));
            u1.x = fmaf(cv1, w1.x, fmaf(mv1, w2.x, u1.x));
            u1.y = fmaf(cv1, w1.y, fmaf(mv1, w2.y, u1.y));
            u1.z = fmaf(cv1, w1.z, fmaf(mv1, w2.z, u1.z));
            u1.w = fmaf(cv1, w1.w, fmaf(mv1, w2.w, u1.w));
        }
        u0.x = fmaxf(u0.x, 0.f); u0.y = fmaxf(u0.y, 0.f);
        u0.z = fmaxf(u0.z, 0.f); u0.w = fmaxf(u0.w, 0.f);
        u1.x = fmaxf(u1.x, 0.f); u1.y = fmaxf(u1.y, 0.f);
        u1.z = fmaxf(u1.z, 0.f); u1.w = fmaxf(u1.w, 0.f);
        *(float4*)&g_cur[dst][b][i0 + il0][fg * 4] = u0;
        *(float4*)&g_cur[dst][b][i0 + il1][fg * 4] = u1;
    }
}

// ---------------- K4: pool + readout precompute ----------------
__global__ void __launch_bounds__(128) k4_pool(const float* __restrict__ Wp,
                                               const float* __restrict__ Wr,
                                               const float* __restrict__ br,
                                               int src) {
    int b = blockIdx.x;
    int tid = threadIdx.x;
    __shared__ float s_part[128];
    __shared__ float s_mean[F];
    __shared__ float s_rp[F];
    __shared__ float s_Wr[OD * 3 * F];   // 768

    for (int t = tid; t < OD * 3 * F; t += 128) s_Wr[t] = Wr[t];

    {
        int f = tid & 63, h = tid >> 6;
        float acc = 0.f;
        for (int i = h; i < NN; i += 2) acc += g_cur[src][b][i][f];
        s_part[tid] = acc;
    }
    __syncthreads();
    if (tid < F) s_mean[tid] = (s_part[tid] + s_part[tid + 64]) * (1.0f / NN);
    __syncthreads();
    if (tid < F) {
        float hp = 0.f;
#pragma unroll 8
        for (int k = 0; k < F; k++) hp = fmaf(s_mean[k], Wp[tid * 64 + k], hp);
        s_rp[tid] = fmaxf(hp, 0.f);
    }
    __syncthreads();
    if (tid < OD) {
        float p = br[tid];
#pragma unroll 8
        for (int f = 0; f < F; f++) p = fmaf(s_rp[f], s_Wr[tid * 192 + f], p);
        g_P[b][tid] = p;
    }
    int i = tid;
    float a[OD] = {0.f, 0.f, 0.f, 0.f};
    float c[OD] = {0.f, 0.f, 0.f, 0.f};
#pragma unroll 4
    for (int k = 0; k < F; k++) {
        float r = fmaxf(g_cur[src][b][i][k], 0.f);
#pragma unroll
        for (int o = 0; o < OD; o++) {
            a[o] = fmaf(r, s_Wr[o * 192 + 64 + k], a[o]);
            c[o] = fmaf(r, s_Wr[o * 192 + 128 + k], c[o]);
        }
    }
#pragma unroll
    for (int o = 0; o < OD; o++) {
        g_A[b][i][o] = a[o];
        g_C[b][i][o] = c[o];
    }
}

// ---------------- K5: output writer ----------------
__global__ void __launch_bounds__(512) k5_out(float* __restrict__ out) {
    int b = blockIdx.y;
    int tid = threadIdx.x;
    int j = tid & 127, iq = tid >> 7;
    int i = blockIdx.x * 4 + iq;
    float4 P = *(const float4*)&g_P[b][0];
    float4 A = *(const float4*)&g_A[b][i][0];
    float4 C = *(const float4*)&g_C[b][j][0];
    float4 r;
    r.x = P.x + A.x + C.x;
    r.y = P.y + A.y + C.y;
    r.z = P.z + A.z + C.z;
    r.w = P.w + A.w + C.w;
    ((float4*)out)[((size_t)b * NN + i) * NN + j] = r;
}

// ---------------- launch ----------------
extern "C" void kernel_launch(void* const* d_in, const int* in_sizes, int n_in,
                              void* d_out, int out_size) {
    const float* obs = (const float*)d_in[0];
    const float* Wi  = (const float*)d_in[1];
    const float* Wee = (const float*)d_in[2];
    const float* Wef = (const float*)d_in[3];
    const float* Wm  = (const float*)d_in[4];
    const float* Wu  = (const float*)d_in[5];
    const float* Wp  = (const float*)d_in[6];
    const float* Wr  = (const float*)d_in[7];
    const float* br  = (const float*)d_in[8];

    static int attr_done = 0;
    if (!attr_done) {
        cudaFuncSetAttribute(k3_layer, cudaFuncAttributeMaxDynamicSharedMemorySize, K3_SMEM_BYTES);
        cudaFuncSetAttribute(k2_edge, cudaFuncAttributeMaxDynamicSharedMemorySize, K2_SMEM_BYTES);
        attr_done = 1;
    }

    k1_init<<<B, 128>>>(obs, Wi, Wee);
    k2_edge<<<dim3(NN / K2_NPB, B), 512, K2_SMEM_BYTES>>>(obs, Wee, Wef);

    const int LW = F * 2 * F;  // 8192 floats per layer
    k3_layer<<<dim3(NN / K3_NPB, B), 256, K3_SMEM_BYTES>>>(obs, Wm + 0 * LW, Wu + 0 * LW, 0, 1);
    k3_layer<<<dim3(NN / K3_NPB, B), 256, K3_SMEM_BYTES>>>(obs, Wm + 1 * LW, Wu + 1 * LW, 1, 0);
    k3_layer<<<dim3(NN / K3_NPB, B), 256, K3_SMEM_BYTES>>>(obs, Wm + 2 * LW, Wu + 2 * LW, 0, 1);

    k4_pool<<<B, 128>>>(Wp, Wr, br, 1);
    k5_out<<<dim3(NN / 4, B), 512>>>((float*)d_out);
}